// round 3
// baseline (speedup 1.0000x reference)
#include <cuda_runtime.h>
#include <cstdint>

#define B_    8
#define V_    4096
#define P_    32
#define CIN   64
#define COUT  128
#define BV    (B_ * V_)      // 32768
#define K2    512

// 64 MB scratch for ypow [BV][K2], k = c*8 + r*4 + l (matches W flattening).
// Values stored pre-rounded to tf32 so K2 can feed mma without cvt.
__device__ float g_ypow[(size_t)BV * K2];

__device__ __forceinline__ uint32_t f2tf32(float x) {
    uint32_t r;
    asm("cvt.rna.tf32.f32 %0, %1;" : "=r"(r) : "f"(x));
    return r;
}

__device__ __forceinline__ void mma_tf32(float& d0, float& d1, float& d2, float& d3,
                                         uint32_t a0, uint32_t a1, uint32_t a2, uint32_t a3,
                                         uint32_t b0, uint32_t b1) {
    asm volatile(
        "mma.sync.aligned.m16n8k8.row.col.f32.tf32.tf32.f32 "
        "{%0,%1,%2,%3}, {%4,%5,%6,%7}, {%8,%9}, {%0,%1,%2,%3};"
        : "+f"(d0), "+f"(d1), "+f"(d2), "+f"(d3)
        : "r"(a0), "r"(a1), "r"(a2), "r"(a3), "r"(b0), "r"(b1));
}

__device__ __forceinline__ float sqclip(float x) {
    return sqrtf(fmaxf(x, 1e-4f));
}

// ---------------------------------------------------------------------------
// Kernel 1: one warp per bv. D[c=64][rn=32] = S^T(64x32p) * A(32p x 32rn),
// fragments loaded directly from gmem (no smem, no syncthreads).
// Epilogue: square + per-l sums via quad butterfly shuffles, coalesced
// float4 stores of sqrt'd power spectrum (pre-rounded tf32).
// ---------------------------------------------------------------------------
__global__ __launch_bounds__(256, 2)
void ypow_kernel(const float* __restrict__ signal,
                 const int*   __restrict__ pidx,
                 const float* __restrict__ convk)
{
    const int warp = threadIdx.x >> 5;
    const int lane = threadIdx.x & 31;
    const int bv   = blockIdx.x * 8 + warp;
    const int g    = lane >> 2;
    const int tig  = lane & 3;

    // Row base for patch p = lane (signal row start, in floats)
    const int2 ip = ((const int2*)pidx)[bv * P_ + lane];
    const int base = (ip.x * V_ + ip.y) * CIN;

    // Distribute bases needed by this lane's fragments: p = 8*ks + tig (+4)
    int bs[4][2];
    #pragma unroll
    for (int ks = 0; ks < 4; ++ks) {
        bs[ks][0] = __shfl_sync(0xffffffffu, base, ks * 8 + tig);
        bs[ks][1] = __shfl_sync(0xffffffffu, base, ks * 8 + tig + 4);
    }

    // B fragments (conv kernel, col-major k x n): load all 32 upfront
    const float* ck = convk + (size_t)bv * 1024;
    uint32_t bf[4][4][2];
    #pragma unroll
    for (int ks = 0; ks < 4; ++ks) {
        #pragma unroll
        for (int nt = 0; nt < 4; ++nt) {
            bf[ks][nt][0] = f2tf32(ck[(ks * 8 + tig)     * 32 + nt * 8 + g]);
            bf[ks][nt][1] = f2tf32(ck[(ks * 8 + tig + 4) * 32 + nt * 8 + g]);
        }
    }

    float4* outp = (float4*)g_ypow + (size_t)bv * 128;

    #pragma unroll
    for (int mt = 0; mt < 4; ++mt) {
        const int m0 = mt * 16;

        float acc[4][4];
        #pragma unroll
        for (int i = 0; i < 4; ++i)
            #pragma unroll
            for (int j = 0; j < 4; ++j) acc[i][j] = 0.0f;

        #pragma unroll
        for (int ks = 0; ks < 4; ++ks) {
            uint32_t a0 = f2tf32(signal[bs[ks][0] + m0 + g]);
            uint32_t a1 = f2tf32(signal[bs[ks][0] + m0 + g + 8]);
            uint32_t a2 = f2tf32(signal[bs[ks][1] + m0 + g]);
            uint32_t a3 = f2tf32(signal[bs[ks][1] + m0 + g + 8]);
            #pragma unroll
            for (int nt = 0; nt < 4; ++nt)
                mma_tf32(acc[nt][0], acc[nt][1], acc[nt][2], acc[nt][3],
                         a0, a1, a2, a3, bf[ks][nt][0], bf[ks][nt][1]);
        }

        // Epilogue: lane (g,tig) holds, for rows {g, g+8}, cols nt*8+2tig+{0,1}.
        // rn = r*16 + n;  l-buckets over n: {0},{1-3},{4-8},{9-15}.
        // Lane's n values: a0 pair -> n = 2tig, 2tig+1; a1 pair -> 8+2tig, 8+2tig+1.
        float pl[2][2][4];   // [h][r][l] partials, statically indexed
        #pragma unroll
        for (int h = 0; h < 2; ++h) {
            #pragma unroll
            for (int r = 0; r < 2; ++r) {
                float v00 = acc[r * 2][h * 2],         v01 = acc[r * 2][h * 2 + 1];
                float v10 = acc[r * 2 + 1][h * 2],     v11 = acc[r * 2 + 1][h * 2 + 1];
                float q00 = v00 * v00, q01 = v01 * v01;
                float q10 = v10 * v10, q11 = v11 * v11;
                float s0 = q00 + q01, s1 = q10 + q11;
                float p0, p1, p2, p3;
                if (tig == 0)      { p0 = q00; p1 = q01;  p2 = q10;  p3 = q11; }
                else if (tig == 1) { p0 = 0;   p1 = s0;   p2 = 0;    p3 = s1;  }
                else               { p0 = 0;   p1 = 0;    p2 = s0;   p3 = s1;  }
                // reduce across the 4 tig lanes of this quad-pair group
                p0 += __shfl_xor_sync(0xffffffffu, p0, 1);
                p1 += __shfl_xor_sync(0xffffffffu, p1, 1);
                p2 += __shfl_xor_sync(0xffffffffu, p2, 1);
                p3 += __shfl_xor_sync(0xffffffffu, p3, 1);
                p0 += __shfl_xor_sync(0xffffffffu, p0, 2);
                p1 += __shfl_xor_sync(0xffffffffu, p1, 2);
                p2 += __shfl_xor_sync(0xffffffffu, p2, 2);
                p3 += __shfl_xor_sync(0xffffffffu, p3, 2);
                pl[h][r][0] = p0; pl[h][r][1] = p1;
                pl[h][r][2] = p2; pl[h][r][3] = p3;
            }
        }
        // Lane tig stores combo (h = tig>>1, r = tig&1): fully coalesced 512B.
        float f0, f1, f2, f3;
        if (tig == 0)      { f0 = pl[0][0][0]; f1 = pl[0][0][1]; f2 = pl[0][0][2]; f3 = pl[0][0][3]; }
        else if (tig == 1) { f0 = pl[0][1][0]; f1 = pl[0][1][1]; f2 = pl[0][1][2]; f3 = pl[0][1][3]; }
        else if (tig == 2) { f0 = pl[1][0][0]; f1 = pl[1][0][1]; f2 = pl[1][0][2]; f3 = pl[1][0][3]; }
        else               { f0 = pl[1][1][0]; f1 = pl[1][1][1]; f2 = pl[1][1][2]; f3 = pl[1][1][3]; }
        float4 o;
        o.x = __uint_as_float(f2tf32(sqclip(f0)));
        o.y = __uint_as_float(f2tf32(sqclip(f1)));
        o.z = __uint_as_float(f2tf32(sqclip(f2)));
        o.w = __uint_as_float(f2tf32(sqclip(f3)));
        outp[mt * 32 + g * 2 + (tig >> 1) * 16 + (tig & 1)] = o;
    }
}

// ---------------------------------------------------------------------------
// Kernel 2: out[32768,128] = ypow * W^T + bias, relu. Direct-LDG fragments,
// no smem. CTA 128m x 128n (8 warps, warp = 32m x 64n). ypow is pre-rounded
// tf32; W converted on the fly (L1-resident).
// ---------------------------------------------------------------------------
__global__ __launch_bounds__(256, 2)
void out_gemm_kernel(const float* __restrict__ W,
                     const float* __restrict__ bias,
                     float* __restrict__ out)
{
    const int warp = threadIdx.x >> 5;
    const int lane = threadIdx.x & 31;
    const int g    = lane >> 2;
    const int tig  = lane & 3;
    const int wm   = warp >> 1;
    const int wn   = warp & 1;
    const int m0   = blockIdx.x * 128 + wm * 32;
    const int n0   = wn * 64;

    float acc[2][8][4];
    #pragma unroll
    for (int a = 0; a < 2; ++a)
        #pragma unroll
        for (int b = 0; b < 8; ++b)
            #pragma unroll
            for (int c = 0; c < 4; ++c) acc[a][b][c] = 0.0f;

    const uint32_t* yp = (const uint32_t*)g_ypow;

    #pragma unroll 4
    for (int kk = 0; kk < 64; ++kk) {
        const int k0 = kk * 8;
        uint32_t a[2][4];
        #pragma unroll
        for (int mi = 0; mi < 2; ++mi) {
            const uint32_t* r0 = yp + (size_t)(m0 + mi * 16 + g) * K2 + k0;
            const uint32_t* r1 = r0 + 8 * K2;
            a[mi][0] = r0[tig];
            a[mi][1] = r1[tig];
            a[mi][2] = r0[tig + 4];
            a[mi][3] = r1[tig + 4];
        }
        #pragma unroll
        for (int nt = 0; nt < 8; ++nt) {
            const float* wr = W + (size_t)(n0 + nt * 8 + g) * K2 + k0;
            uint32_t b0 = f2tf32(wr[0 + tig]);
            uint32_t b1 = f2tf32(wr[4 + tig]);
            mma_tf32(acc[0][nt][0], acc[0][nt][1], acc[0][nt][2], acc[0][nt][3],
                     a[0][0], a[0][1], a[0][2], a[0][3], b0, b1);
            mma_tf32(acc[1][nt][0], acc[1][nt][1], acc[1][nt][2], acc[1][nt][3],
                     a[1][0], a[1][1], a[1][2], a[1][3], b0, b1);
        }
    }

    // Epilogue: bias + relu, float2 stores
    #pragma unroll
    for (int nt = 0; nt < 8; ++nt) {
        const int col = n0 + nt * 8 + 2 * tig;
        const float b0 = __ldg(&bias[col]);
        const float b1 = __ldg(&bias[col + 1]);
        #pragma unroll
        for (int mi = 0; mi < 2; ++mi) {
            const int row = m0 + mi * 16 + g;
            float2 v0, v1;
            v0.x = fmaxf(acc[mi][nt][0] + b0, 0.0f);
            v0.y = fmaxf(acc[mi][nt][1] + b1, 0.0f);
            v1.x = fmaxf(acc[mi][nt][2] + b0, 0.0f);
            v1.y = fmaxf(acc[mi][nt][3] + b1, 0.0f);
            *(float2*)(out + (size_t)row * COUT + col)       = v0;
            *(float2*)(out + (size_t)(row + 8) * COUT + col) = v1;
        }
    }
}

extern "C" void kernel_launch(void* const* d_in, const int* in_sizes, int n_in,
                              void* d_out, int out_size)
{
    const float* signal = (const float*)d_in[0];
    const int*   pidx   = (const int*)  d_in[1];
    const float* convk  = (const float*)d_in[2];
    const float* W      = (const float*)d_in[3];
    const float* bias   = (const float*)d_in[4];
    float* out = (float*)d_out;

    ypow_kernel<<<BV / 8, 256>>>(signal, pidx, convk);
    out_gemm_kernel<<<BV / 128, 256>>>(W, bias, out);
}

// round 4
// speedup vs baseline: 1.7242x; 1.7242x over previous
#include <cuda_runtime.h>
#include <cstdint>

#define B_    8
#define V_    4096
#define P_    32
#define CIN   64
#define COUT  128
#define BV    (B_ * V_)      // 32768
#define K2    512

// ypow [BV][K2] scratch, k = c*8 + r*4 + l (matches W flattening), tf32 bits.
__device__ float g_ypow[(size_t)BV * K2];
// W pre-converted to tf32 bits
__device__ uint32_t g_W[(size_t)COUT * K2];

__device__ __forceinline__ uint32_t f2tf32(float x) {
    uint32_t r;
    asm("cvt.rna.tf32.f32 %0, %1;" : "=r"(r) : "f"(x));
    return r;
}

__device__ __forceinline__ void mma_tf32(float& d0, float& d1, float& d2, float& d3,
                                         uint32_t a0, uint32_t a1, uint32_t a2, uint32_t a3,
                                         uint32_t b0, uint32_t b1) {
    asm volatile(
        "mma.sync.aligned.m16n8k8.row.col.f32.tf32.tf32.f32 "
        "{%0,%1,%2,%3}, {%4,%5,%6,%7}, {%8,%9}, {%0,%1,%2,%3};"
        : "+f"(d0), "+f"(d1), "+f"(d2), "+f"(d3)
        : "r"(a0), "r"(a1), "r"(a2), "r"(a3), "r"(b0), "r"(b1));
}

__device__ __forceinline__ float sqclip(float x) {
    return sqrtf(fmaxf(x, 1e-4f));
}

__device__ __forceinline__ uint32_t smem_u32(const void* p) {
    return (uint32_t)__cvta_generic_to_shared(p);
}

__device__ __forceinline__ void cp_async16(uint32_t dst, const void* src) {
    asm volatile("cp.async.cg.shared.global [%0], [%1], 16;" :: "r"(dst), "l"(src));
}

// ---------------------------------------------------------------------------
// Prologue: W -> tf32 bits (once per launch, ~2us)
// ---------------------------------------------------------------------------
__global__ void wcvt_kernel(const float* __restrict__ W) {
    int i = blockIdx.x * 256 + threadIdx.x;
    g_W[i] = f2tf32(W[i]);
}

// ---------------------------------------------------------------------------
// Kernel 1: one warp per bv.  D[rn=32][c=64] = ck^T(32x32p) * S(32p x 64c).
// Natural-layout staging (no transpose): A-frag reads sCK[k][m], B-frag reads
// sS[k][n] -- both conflict-free via stride pads. Epilogue: acc -> sY[c][rn],
// column LDS.128 reads, per-l bucket sums, sqrt, coalesced float4 STG.
// CTA = 64 threads = 2 warps = 2 bv (warp-independent; no __syncthreads).
// ---------------------------------------------------------------------------
#define SS_STR 72   // sS [p=32][c=64]pad : frag banks 8*tig + 8*nt + g, distinct
#define CK_STR 40   // sCK[p=32][rn=32]pad: frag banks 8*tig + g (+16mt), distinct
#define SY_STR 36   // sY [c=64][rn=32]pad: col LDS.128 4-phase perfect

__global__ __launch_bounds__(64)
void ypow_kernel(const float* __restrict__ signal,
                 const int*   __restrict__ pidx,
                 const float* __restrict__ convk)
{
    __shared__ uint32_t smem[2][32 * SS_STR + 32 * CK_STR];   // 28672 B

    const int warp = threadIdx.x >> 5;
    const int lane = threadIdx.x & 31;
    const int bv   = blockIdx.x * 2 + warp;
    const int g    = lane >> 2;
    const int tig  = lane & 3;

    uint32_t* sS  = smem[warp];                 // [32][72] = 2304 words
    uint32_t* sCK = smem[warp] + 32 * SS_STR;   // [32][40] = 1280 words
    uint32_t* sY  = smem[warp];                 // overlay: [64][36] = 2304 words

    // lane p = lane: gathered signal row base (in floats)
    const int2 ip = ((const int2*)pidx)[bv * P_ + lane];
    const int base = (ip.x * V_ + ip.y) * CIN;

    // Stage ck [p][rn]: 256 float4, coalesced
    {
        const float4* ck4 = (const float4*)(convk + (size_t)bv * 1024);
        #pragma unroll
        for (int j = 0; j < 8; ++j) {
            int f = j * 32 + lane;
            float4 v = ck4[f];
            int p = f >> 3, q = f & 7;
            uint4 u;
            u.x = f2tf32(v.x); u.y = f2tf32(v.y); u.z = f2tf32(v.z); u.w = f2tf32(v.w);
            *(uint4*)&sCK[p * CK_STR + q * 4] = u;
        }
    }
    // Stage S [p][c]: 512 float4, rows gathered, natural layout (no transpose)
    {
        #pragma unroll
        for (int j = 0; j < 16; ++j) {
            int f = j * 32 + lane;
            int p = f >> 4, q = f & 15;
            int bp = __shfl_sync(0xffffffffu, base, p);
            float4 v = *(const float4*)(signal + bp + q * 4);
            uint4 u;
            u.x = f2tf32(v.x); u.y = f2tf32(v.y); u.z = f2tf32(v.z); u.w = f2tf32(v.w);
            *(uint4*)&sS[p * SS_STR + q * 4] = u;
        }
    }
    __syncwarp();

    // Warp computes whole bv: 2 m-tiles (rn) x 8 n-tiles (c) x 4 k-steps
    float acc[2][8][4];
    #pragma unroll
    for (int i = 0; i < 2; ++i)
        #pragma unroll
        for (int j = 0; j < 8; ++j)
            #pragma unroll
            for (int e = 0; e < 4; ++e) acc[i][j][e] = 0.0f;

    #pragma unroll
    for (int ks = 0; ks < 4; ++ks) {
        const int k0 = ks * 8;
        uint32_t a[2][4];
        #pragma unroll
        for (int mt = 0; mt < 2; ++mt) {
            a[mt][0] = sCK[(k0 + tig)     * CK_STR + mt * 16 + g];
            a[mt][1] = sCK[(k0 + tig)     * CK_STR + mt * 16 + g + 8];
            a[mt][2] = sCK[(k0 + tig + 4) * CK_STR + mt * 16 + g];
            a[mt][3] = sCK[(k0 + tig + 4) * CK_STR + mt * 16 + g + 8];
        }
        #pragma unroll
        for (int nt = 0; nt < 8; ++nt) {
            uint32_t b0 = sS[(k0 + tig)     * SS_STR + nt * 8 + g];
            uint32_t b1 = sS[(k0 + tig + 4) * SS_STR + nt * 8 + g];
            mma_tf32(acc[0][nt][0], acc[0][nt][1], acc[0][nt][2], acc[0][nt][3],
                     a[0][0], a[0][1], a[0][2], a[0][3], b0, b1);
            mma_tf32(acc[1][nt][0], acc[1][nt][1], acc[1][nt][2], acc[1][nt][3],
                     a[1][0], a[1][1], a[1][2], a[1][3], b0, b1);
        }
    }
    __syncwarp();

    // acc -> sY[c][rn] (stride 36). d0:(mt*16+g, c) d1:(.., c+1) d2:(+8 row) d3.
    #pragma unroll
    for (int mt = 0; mt < 2; ++mt) {
        #pragma unroll
        for (int nt = 0; nt < 8; ++nt) {
            const int c  = nt * 8 + 2 * tig;
            const int r0 = mt * 16 + g;
            sY[(c)     * SY_STR + r0]     = __float_as_uint(acc[mt][nt][0]);
            sY[(c + 1) * SY_STR + r0]     = __float_as_uint(acc[mt][nt][1]);
            sY[(c)     * SY_STR + r0 + 8] = __float_as_uint(acc[mt][nt][2]);
            sY[(c + 1) * SY_STR + r0 + 8] = __float_as_uint(acc[mt][nt][3]);
        }
    }
    __syncwarp();

    // Epilogue: lane handles (c, r) pairs; v[n] = D[r*16+n][c]; l-bucket sums.
    float4* outp = (float4*)g_ypow + (size_t)bv * 128;
    #pragma unroll
    for (int i = 0; i < 4; ++i) {
        const int c = i * 16 + (lane >> 1);
        const int r = lane & 1;
        const uint32_t* col = sY + c * SY_STR + r * 16;
        uint4 q0 = *(const uint4*)&col[0];
        uint4 q1 = *(const uint4*)&col[4];
        uint4 q2 = *(const uint4*)&col[8];
        uint4 q3 = *(const uint4*)&col[12];
        float v0  = __uint_as_float(q0.x), v1  = __uint_as_float(q0.y);
        float v2  = __uint_as_float(q0.z), v3  = __uint_as_float(q0.w);
        float v4  = __uint_as_float(q1.x), v5  = __uint_as_float(q1.y);
        float v6  = __uint_as_float(q1.z), v7  = __uint_as_float(q1.w);
        float v8  = __uint_as_float(q2.x), v9  = __uint_as_float(q2.y);
        float v10 = __uint_as_float(q2.z), v11 = __uint_as_float(q2.w);
        float v12 = __uint_as_float(q3.x), v13 = __uint_as_float(q3.y);
        float v14 = __uint_as_float(q3.z), v15 = __uint_as_float(q3.w);
        float l0 = v0 * v0;
        float l1 = v1 * v1 + v2 * v2 + v3 * v3;
        float l2 = v4 * v4 + v5 * v5 + v6 * v6 + v7 * v7 + v8 * v8;
        float l3 = v9 * v9 + v10 * v10 + v11 * v11 + v12 * v12
                 + v13 * v13 + v14 * v14 + v15 * v15;
        float4 o;
        o.x = __uint_as_float(f2tf32(sqclip(l0)));
        o.y = __uint_as_float(f2tf32(sqclip(l1)));
        o.z = __uint_as_float(f2tf32(sqclip(l2)));
        o.w = __uint_as_float(f2tf32(sqclip(l3)));
        outp[c * 2 + r] = o;   // = i*32 + lane : coalesced
    }
}

// ---------------------------------------------------------------------------
// Kernel 2: out[32768,128] = ypow * W^T + bias, relu.  tf32 mma, smem-staged
// via cp.async double buffer (kT=16, stride 20).  CTA 128m x 128n, 8 warps
// each 32m x 64n.  Zero cvt (both operands pre-tf32).
// ---------------------------------------------------------------------------
#define KT    16
#define TSTR  20   // (20g + tig) mod 32 distinct -> conflict-free frags

__global__ __launch_bounds__(256, 2)
void out_gemm_kernel(const float* __restrict__ bias,
                     float* __restrict__ out)
{
    __shared__ uint32_t sA[2][128 * TSTR];   // ypow tile [m][k], 10240 B/stage
    __shared__ uint32_t sB[2][128 * TSTR];   // W    tile [n][k]

    const int tid  = threadIdx.x;
    const int warp = tid >> 5;
    const int lane = tid & 31;
    const int g    = lane >> 2;
    const int tig  = lane & 3;
    const int wm   = warp >> 1;
    const int wn   = warp & 1;
    const int m0   = blockIdx.x * 128;

    const uint32_t* yp = (const uint32_t*)g_ypow;

    float acc[2][8][4];
    #pragma unroll
    for (int a = 0; a < 2; ++a)
        #pragma unroll
        for (int b = 0; b < 8; ++b)
            #pragma unroll
            for (int c = 0; c < 4; ++c) acc[a][b][c] = 0.0f;

    // async stage of k-tile kt into buffer st
    auto stage = [&](int kt, int st) {
        #pragma unroll
        for (int it = 0; it < 2; ++it) {
            int f = tid + it * 256;          // 0..511 float4 slots
            int row = f >> 2, kq = f & 3;
            cp_async16(smem_u32(&sA[st][row * TSTR + kq * 4]),
                       yp + (size_t)(m0 + row) * K2 + kt * KT + kq * 4);
            cp_async16(smem_u32(&sB[st][row * TSTR + kq * 4]),
                       g_W + (size_t)row * K2 + kt * KT + kq * 4);
        }
        asm volatile("cp.async.commit_group;");
    };

    stage(0, 0);

    for (int kt = 0; kt < K2 / KT; ++kt) {
        const int st = kt & 1;
        asm volatile("cp.async.wait_group 0;");
        __syncthreads();
        if (kt + 1 < K2 / KT) stage(kt + 1, st ^ 1);

        #pragma unroll
        for (int ks = 0; ks < 2; ++ks) {
            const int k0 = ks * 8;
            uint32_t a[2][4];
            #pragma unroll
            for (int mi = 0; mi < 2; ++mi) {
                const int mr = wm * 32 + mi * 16;
                a[mi][0] = sA[st][(mr + g)     * TSTR + k0 + tig];
                a[mi][1] = sA[st][(mr + g + 8) * TSTR + k0 + tig];
                a[mi][2] = sA[st][(mr + g)     * TSTR + k0 + tig + 4];
                a[mi][3] = sA[st][(mr + g + 8) * TSTR + k0 + tig + 4];
            }
            #pragma unroll
            for (int nt = 0; nt < 8; ++nt) {
                const int n = wn * 64 + nt * 8 + g;
                uint32_t b0 = sB[st][n * TSTR + k0 + tig];
                uint32_t b1 = sB[st][n * TSTR + k0 + tig + 4];
                mma_tf32(acc[0][nt][0], acc[0][nt][1], acc[0][nt][2], acc[0][nt][3],
                         a[0][0], a[0][1], a[0][2], a[0][3], b0, b1);
                mma_tf32(acc[1][nt][0], acc[1][nt][1], acc[1][nt][2], acc[1][nt][3],
                         a[1][0], a[1][1], a[1][2], a[1][3], b0, b1);
            }
        }
        __syncthreads();
    }

    // Epilogue: bias + relu, float2 stores
    #pragma unroll
    for (int nt = 0; nt < 8; ++nt) {
        const int col = wn * 64 + nt * 8 + 2 * tig;
        const float b0 = __ldg(&bias[col]);
        const float b1 = __ldg(&bias[col + 1]);
        #pragma unroll
        for (int mi = 0; mi < 2; ++mi) {
            const int row = m0 + wm * 32 + mi * 16 + g;
            float2 v0, v1;
            v0.x = fmaxf(acc[mi][nt][0] + b0, 0.0f);
            v0.y = fmaxf(acc[mi][nt][1] + b1, 0.0f);
            v1.x = fmaxf(acc[mi][nt][2] + b0, 0.0f);
            v1.y = fmaxf(acc[mi][nt][3] + b1, 0.0f);
            *(float2*)(out + (size_t)row * COUT + col)       = v0;
            *(float2*)(out + (size_t)(row + 8) * COUT + col) = v1;
        }
    }
}

extern "C" void kernel_launch(void* const* d_in, const int* in_sizes, int n_in,
                              void* d_out, int out_size)
{
    const float* signal = (const float*)d_in[0];
    const int*   pidx   = (const int*)  d_in[1];
    const float* convk  = (const float*)d_in[2];
    const float* W      = (const float*)d_in[3];
    const float* bias   = (const float*)d_in[4];
    float* out = (float*)d_out;

    wcvt_kernel<<<COUT * K2 / 256, 256>>>(W);
    ypow_kernel<<<BV / 2, 64>>>(signal, pidx, convk);
    out_gemm_kernel<<<BV / 128, 256>>>(bias, out);
}

// round 5
// speedup vs baseline: 1.8064x; 1.0477x over previous
#include <cuda_runtime.h>
#include <cstdint>

#define B_    8
#define V_    4096
#define P_    32
#define CIN   64
#define COUT  128
#define BV    (B_ * V_)      // 32768
#define K2    512

// ypow [BV][K2] scratch, k = c*8 + r*4 + l (matches W flattening), tf32 bits.
__device__ float g_ypow[(size_t)BV * K2];
// W pre-converted to tf32 bits (filled by first 1024 CTAs of ypow_kernel)
__device__ uint32_t g_W[(size_t)COUT * K2];

__device__ __forceinline__ uint32_t f2tf32(float x) {
    uint32_t r;
    asm("cvt.rna.tf32.f32 %0, %1;" : "=r"(r) : "f"(x));
    return r;
}

__device__ __forceinline__ void mma_tf32(float& d0, float& d1, float& d2, float& d3,
                                         uint32_t a0, uint32_t a1, uint32_t a2, uint32_t a3,
                                         uint32_t b0, uint32_t b1) {
    asm volatile(
        "mma.sync.aligned.m16n8k8.row.col.f32.tf32.tf32.f32 "
        "{%0,%1,%2,%3}, {%4,%5,%6,%7}, {%8,%9}, {%0,%1,%2,%3};"
        : "+f"(d0), "+f"(d1), "+f"(d2), "+f"(d3)
        : "r"(a0), "r"(a1), "r"(a2), "r"(a3), "r"(b0), "r"(b1));
}

__device__ __forceinline__ float sqclip(float x) {
    return sqrtf(fmaxf(x, 1e-4f));
}

__device__ __forceinline__ uint32_t smem_u32(const void* p) {
    return (uint32_t)__cvta_generic_to_shared(p);
}

__device__ __forceinline__ void cp_async16(uint32_t dst, const void* src) {
    asm volatile("cp.async.cg.shared.global [%0], [%1], 16;" :: "r"(dst), "l"(src));
}

// ---------------------------------------------------------------------------
// Kernel 1: CTA = 64 threads = 2 warps = ONE bv.
// D[rn=32][c=64] = ck^T(32x32p) * S(32p x 64c); warp h owns c-half h (32 cols).
// acc = 32 regs/lane -> high occupancy. sCK shared, sS split per warp.
// Epilogue: acc -> sY[c'][rn] overlay (own S half), column LDS.128, l-sums,
// sqrt, coalesced float4 STG. First 1024 CTAs also convert W -> tf32.
// ---------------------------------------------------------------------------
#define CK_STR 40   // frag banks 8*tig + g (+16mt) distinct
#define SH_STR 40   // S half [p=32][c'=32] pad; frag banks 8*tig + 8nt + g distinct
#define SY_STR 36   // column LDS.128 4-phase conflict-free

__global__ __launch_bounds__(64, 14)
void ypow_kernel(const float* __restrict__ signal,
                 const int*   __restrict__ pidx,
                 const float* __restrict__ convk,
                 const float* __restrict__ W)
{
    __shared__ uint32_t sCK[32 * CK_STR];      // 5120 B
    __shared__ uint32_t sSh[2][32 * SH_STR];   // 2 x 5120 B

    const int tid  = threadIdx.x;
    const int warp = tid >> 5;      // = c-half h
    const int lane = tid & 31;
    const int bv   = blockIdx.x;
    const int g    = lane >> 2;
    const int tig  = lane & 3;

    // Fold W -> tf32 conversion into the first 1024 CTAs (1 elem/thread)
    if (blockIdx.x < 1024)
        g_W[blockIdx.x * 64 + tid] = f2tf32(W[blockIdx.x * 64 + tid]);

    // lane p = lane: gathered signal row base (in floats)
    const int2 ip = ((const int2*)pidx)[bv * P_ + lane];
    const int base = (ip.x * V_ + ip.y) * CIN;

    // Stage ck [p][rn]: 256 float4, both warps, coalesced
    {
        const float4* ck4 = (const float4*)(convk + (size_t)bv * 1024);
        #pragma unroll
        for (int j = 0; j < 4; ++j) {
            int f = j * 64 + tid;
            float4 v = ck4[f];
            int p = f >> 3, q = f & 7;
            uint4 u;
            u.x = f2tf32(v.x); u.y = f2tf32(v.y); u.z = f2tf32(v.z); u.w = f2tf32(v.w);
            *(uint4*)&sCK[p * CK_STR + q * 4] = u;
        }
    }
    // Stage own S half [p][c' 0..31]: 256 float4 per warp
    {
        uint32_t* sS = sSh[warp];
        #pragma unroll
        for (int j = 0; j < 8; ++j) {
            int f = j * 32 + lane;
            int p = f >> 3, q = f & 7;
            int bp = __shfl_sync(0xffffffffu, base, p);
            float4 v = *(const float4*)(signal + bp + (warp * 8 + q) * 4);
            uint4 u;
            u.x = f2tf32(v.x); u.y = f2tf32(v.y); u.z = f2tf32(v.z); u.w = f2tf32(v.w);
            *(uint4*)&sS[p * SH_STR + q * 4] = u;
        }
    }
    __syncthreads();   // sCK written by both warps

    // Warp computes D[rn=32][its 32 c']: 2 mt x 4 nt x 4 ks
    const uint32_t* sS = sSh[warp];
    float acc[2][4][4];
    #pragma unroll
    for (int i = 0; i < 2; ++i)
        #pragma unroll
        for (int j = 0; j < 4; ++j)
            #pragma unroll
            for (int e = 0; e < 4; ++e) acc[i][j][e] = 0.0f;

    #pragma unroll
    for (int ks = 0; ks < 4; ++ks) {
        const int k0 = ks * 8;
        uint32_t a[2][4];
        #pragma unroll
        for (int mt = 0; mt < 2; ++mt) {
            a[mt][0] = sCK[(k0 + tig)     * CK_STR + mt * 16 + g];
            a[mt][1] = sCK[(k0 + tig)     * CK_STR + mt * 16 + g + 8];
            a[mt][2] = sCK[(k0 + tig + 4) * CK_STR + mt * 16 + g];
            a[mt][3] = sCK[(k0 + tig + 4) * CK_STR + mt * 16 + g + 8];
        }
        #pragma unroll
        for (int nt = 0; nt < 4; ++nt) {
            uint32_t b0 = sS[(k0 + tig)     * SH_STR + nt * 8 + g];
            uint32_t b1 = sS[(k0 + tig + 4) * SH_STR + nt * 8 + g];
            mma_tf32(acc[0][nt][0], acc[0][nt][1], acc[0][nt][2], acc[0][nt][3],
                     a[0][0], a[0][1], a[0][2], a[0][3], b0, b1);
            mma_tf32(acc[1][nt][0], acc[1][nt][1], acc[1][nt][2], acc[1][nt][3],
                     a[1][0], a[1][1], a[1][2], a[1][3], b0, b1);
        }
    }
    __syncwarp();   // done reading own sS half; overlay it with sY

    // acc -> sY[c'][rn] (stride 36), own-warp overlay region
    uint32_t* sY = sSh[warp];   // [32][36] = 1152 words <= 1280
    #pragma unroll
    for (int mt = 0; mt < 2; ++mt) {
        #pragma unroll
        for (int nt = 0; nt < 4; ++nt) {
            const int c  = nt * 8 + 2 * tig;
            const int r0 = mt * 16 + g;
            sY[(c)     * SY_STR + r0]     = __float_as_uint(acc[mt][nt][0]);
            sY[(c + 1) * SY_STR + r0]     = __float_as_uint(acc[mt][nt][1]);
            sY[(c)     * SY_STR + r0 + 8] = __float_as_uint(acc[mt][nt][2]);
            sY[(c + 1) * SY_STR + r0 + 8] = __float_as_uint(acc[mt][nt][3]);
        }
    }
    __syncwarp();

    // Epilogue: 32 c' x 2 r pairs / 32 lanes = 2 each; l-bucket sums + sqrt
    float4* outp = (float4*)g_ypow + (size_t)bv * 128 + warp * 64;
    #pragma unroll
    for (int i = 0; i < 2; ++i) {
        const int c = i * 16 + (lane >> 1);
        const int r = lane & 1;
        const uint32_t* col = sY + c * SY_STR + r * 16;
        uint4 q0 = *(const uint4*)&col[0];
        uint4 q1 = *(const uint4*)&col[4];
        uint4 q2 = *(const uint4*)&col[8];
        uint4 q3 = *(const uint4*)&col[12];
        float v0  = __uint_as_float(q0.x), v1  = __uint_as_float(q0.y);
        float v2  = __uint_as_float(q0.z), v3  = __uint_as_float(q0.w);
        float v4  = __uint_as_float(q1.x), v5  = __uint_as_float(q1.y);
        float v6  = __uint_as_float(q1.z), v7  = __uint_as_float(q1.w);
        float v8  = __uint_as_float(q2.x), v9  = __uint_as_float(q2.y);
        float v10 = __uint_as_float(q2.z), v11 = __uint_as_float(q2.w);
        float v12 = __uint_as_float(q3.x), v13 = __uint_as_float(q3.y);
        float v14 = __uint_as_float(q3.z), v15 = __uint_as_float(q3.w);
        float l0 = v0 * v0;
        float l1 = v1 * v1 + v2 * v2 + v3 * v3;
        float l2 = v4 * v4 + v5 * v5 + v6 * v6 + v7 * v7 + v8 * v8;
        float l3 = v9 * v9 + v10 * v10 + v11 * v11 + v12 * v12
                 + v13 * v13 + v14 * v14 + v15 * v15;
        float4 o;
        o.x = __uint_as_float(f2tf32(sqclip(l0)));
        o.y = __uint_as_float(f2tf32(sqclip(l1)));
        o.z = __uint_as_float(f2tf32(sqclip(l2)));
        o.w = __uint_as_float(f2tf32(sqclip(l3)));
        outp[c * 2 + r] = o;   // = i*32 + lane within half: coalesced
    }
}

// ---------------------------------------------------------------------------
// Kernel 2: out[32768,128] = ypow * W^T + bias, relu.  tf32 mma, cp.async
// double buffer with stage-ahead overlap (kT=16, stride 20).  CTA 128m x 128n,
// 8 warps each 32m x 64n.  Zero cvt (both operands pre-tf32).
// ---------------------------------------------------------------------------
#define KT    16
#define NKT   (K2 / KT)
#define TSTR  20   // (20g + tig) mod 32 distinct -> conflict-free frags

__global__ __launch_bounds__(256, 2)
void out_gemm_kernel(const float* __restrict__ bias,
                     float* __restrict__ out)
{
    __shared__ uint32_t sA[2][128 * TSTR];
    __shared__ uint32_t sB[2][128 * TSTR];

    const int tid  = threadIdx.x;
    const int warp = tid >> 5;
    const int lane = tid & 31;
    const int g    = lane >> 2;
    const int tig  = lane & 3;
    const int wm   = warp >> 1;
    const int wn   = warp & 1;
    const int m0   = blockIdx.x * 128;

    const uint32_t* yp = (const uint32_t*)g_ypow;

    float acc[2][8][4];
    #pragma unroll
    for (int a = 0; a < 2; ++a)
        #pragma unroll
        for (int b = 0; b < 8; ++b)
            #pragma unroll
            for (int c = 0; c < 4; ++c) acc[a][b][c] = 0.0f;

    auto stage = [&](int kt, int st) {
        #pragma unroll
        for (int it = 0; it < 2; ++it) {
            int f = tid + it * 256;          // 0..511 float4 slots
            int row = f >> 2, kq = f & 3;
            cp_async16(smem_u32(&sA[st][row * TSTR + kq * 4]),
                       yp + (size_t)(m0 + row) * K2 + kt * KT + kq * 4);
            cp_async16(smem_u32(&sB[st][row * TSTR + kq * 4]),
                       g_W + (size_t)row * K2 + kt * KT + kq * 4);
        }
        asm volatile("cp.async.commit_group;");
    };

    stage(0, 0);

    for (int kt = 0; kt < NKT; ++kt) {
        const int st = kt & 1;
        // Stage-ahead: issue kt+1 before waiting on kt (overlap with compute).
        if (kt + 1 < NKT) {
            stage(kt + 1, st ^ 1);
            asm volatile("cp.async.wait_group 1;");
        } else {
            asm volatile("cp.async.wait_group 0;");
        }
        __syncthreads();

        #pragma unroll
        for (int ks = 0; ks < 2; ++ks) {
            const int k0 = ks * 8;
            uint32_t a[2][4];
            #pragma unroll
            for (int mi = 0; mi < 2; ++mi) {
                const int mr = wm * 32 + mi * 16;
                a[mi][0] = sA[st][(mr + g)     * TSTR + k0 + tig];
                a[mi][1] = sA[st][(mr + g + 8) * TSTR + k0 + tig];
                a[mi][2] = sA[st][(mr + g)     * TSTR + k0 + tig + 4];
                a[mi][3] = sA[st][(mr + g + 8) * TSTR + k0 + tig + 4];
            }
            #pragma unroll
            for (int nt = 0; nt < 8; ++nt) {
                const int n = wn * 64 + nt * 8 + g;
                uint32_t b0 = sB[st][n * TSTR + k0 + tig];
                uint32_t b1 = sB[st][n * TSTR + k0 + tig + 4];
                mma_tf32(acc[0][nt][0], acc[0][nt][1], acc[0][nt][2], acc[0][nt][3],
                         a[0][0], a[0][1], a[0][2], a[0][3], b0, b1);
                mma_tf32(acc[1][nt][0], acc[1][nt][1], acc[1][nt][2], acc[1][nt][3],
                         a[1][0], a[1][1], a[1][2], a[1][3], b0, b1);
            }
        }
        __syncthreads();   // buffer st free for stage(kt+2)
    }

    // Epilogue: bias + relu, float2 stores
    #pragma unroll
    for (int nt = 0; nt < 8; ++nt) {
        const int col = wn * 64 + nt * 8 + 2 * tig;
        const float b0 = __ldg(&bias[col]);
        const float b1 = __ldg(&bias[col + 1]);
        #pragma unroll
        for (int mi = 0; mi < 2; ++mi) {
            const int row = m0 + wm * 32 + mi * 16 + g;
            float2 v0, v1;
            v0.x = fmaxf(acc[mi][nt][0] + b0, 0.0f);
            v0.y = fmaxf(acc[mi][nt][1] + b1, 0.0f);
            v1.x = fmaxf(acc[mi][nt][2] + b0, 0.0f);
            v1.y = fmaxf(acc[mi][nt][3] + b1, 0.0f);
            *(float2*)(out + (size_t)row * COUT + col)       = v0;
            *(float2*)(out + (size_t)(row + 8) * COUT + col) = v1;
        }
    }
}

extern "C" void kernel_launch(void* const* d_in, const int* in_sizes, int n_in,
                              void* d_out, int out_size)
{
    const float* signal = (const float*)d_in[0];
    const int*   pidx   = (const int*)  d_in[1];
    const float* convk  = (const float*)d_in[2];
    const float* W      = (const float*)d_in[3];
    const float* bias   = (const float*)d_in[4];
    float* out = (float*)d_out;

    ypow_kernel<<<BV, 64>>>(signal, pidx, convk, W);
    out_gemm_kernel<<<BV / 128, 256>>>(bias, out);
}

// round 6
// speedup vs baseline: 1.9698x; 1.0905x over previous
#include <cuda_runtime.h>
#include <cstdint>

#define B_    8
#define V_    4096
#define P_    32
#define CIN   64
#define COUT  128
#define BV    (B_ * V_)      // 32768
#define K2    512

// ypow [BV][K2] scratch, k = c*8 + r*4 + l (matches W flattening), tf32 bits.
__device__ float g_ypow[(size_t)BV * K2];
// W pre-converted to tf32 bits (filled by first 1024 CTAs of ypow_kernel)
__device__ uint32_t g_W[(size_t)COUT * K2];

__device__ __forceinline__ uint32_t f2tf32(float x) {
    uint32_t r;
    asm("cvt.rna.tf32.f32 %0, %1;" : "=r"(r) : "f"(x));
    return r;
}

__device__ __forceinline__ void mma_tf32(float& d0, float& d1, float& d2, float& d3,
                                         uint32_t a0, uint32_t a1, uint32_t a2, uint32_t a3,
                                         uint32_t b0, uint32_t b1) {
    asm volatile(
        "mma.sync.aligned.m16n8k8.row.col.f32.tf32.tf32.f32 "
        "{%0,%1,%2,%3}, {%4,%5,%6,%7}, {%8,%9}, {%0,%1,%2,%3};"
        : "+f"(d0), "+f"(d1), "+f"(d2), "+f"(d3)
        : "r"(a0), "r"(a1), "r"(a2), "r"(a3), "r"(b0), "r"(b1));
}

__device__ __forceinline__ void ldsm_x4(uint32_t* r, uint32_t addr) {
    asm volatile("ldmatrix.sync.aligned.m8n8.x4.shared.b16 {%0,%1,%2,%3}, [%4];"
        : "=r"(r[0]), "=r"(r[1]), "=r"(r[2]), "=r"(r[3]) : "r"(addr));
}

__device__ __forceinline__ float sqclip(float x) {
    return sqrtf(fmaxf(x, 1e-4f));
}

__device__ __forceinline__ uint32_t smem_u32(const void* p) {
    return (uint32_t)__cvta_generic_to_shared(p);
}

__device__ __forceinline__ void cp_async16(uint32_t dst, const void* src) {
    asm volatile("cp.async.cg.shared.global [%0], [%1], 16;" :: "r"(dst), "l"(src));
}

// ---------------------------------------------------------------------------
// Kernel 1: CTA = 64 threads = 2 warps = ONE bv (unchanged from R5).
// ---------------------------------------------------------------------------
#define CK_STR 40
#define SH_STR 40
#define SY_STR 36

__global__ __launch_bounds__(64, 14)
void ypow_kernel(const float* __restrict__ signal,
                 const int*   __restrict__ pidx,
                 const float* __restrict__ convk,
                 const float* __restrict__ W)
{
    __shared__ uint32_t sCK[32 * CK_STR];
    __shared__ uint32_t sSh[2][32 * SH_STR];

    const int tid  = threadIdx.x;
    const int warp = tid >> 5;
    const int lane = tid & 31;
    const int bv   = blockIdx.x;
    const int g    = lane >> 2;
    const int tig  = lane & 3;

    if (blockIdx.x < 1024)
        g_W[blockIdx.x * 64 + tid] = f2tf32(W[blockIdx.x * 64 + tid]);

    const int2 ip = ((const int2*)pidx)[bv * P_ + lane];
    const int base = (ip.x * V_ + ip.y) * CIN;

    {
        const float4* ck4 = (const float4*)(convk + (size_t)bv * 1024);
        #pragma unroll
        for (int j = 0; j < 4; ++j) {
            int f = j * 64 + tid;
            float4 v = ck4[f];
            int p = f >> 3, q = f & 7;
            uint4 u;
            u.x = f2tf32(v.x); u.y = f2tf32(v.y); u.z = f2tf32(v.z); u.w = f2tf32(v.w);
            *(uint4*)&sCK[p * CK_STR + q * 4] = u;
        }
    }
    {
        uint32_t* sS = sSh[warp];
        #pragma unroll
        for (int j = 0; j < 8; ++j) {
            int f = j * 32 + lane;
            int p = f >> 3, q = f & 7;
            int bp = __shfl_sync(0xffffffffu, base, p);
            float4 v = *(const float4*)(signal + bp + (warp * 8 + q) * 4);
            uint4 u;
            u.x = f2tf32(v.x); u.y = f2tf32(v.y); u.z = f2tf32(v.z); u.w = f2tf32(v.w);
            *(uint4*)&sS[p * SH_STR + q * 4] = u;
        }
    }
    __syncthreads();

    const uint32_t* sS = sSh[warp];
    float acc[2][4][4];
    #pragma unroll
    for (int i = 0; i < 2; ++i)
        #pragma unroll
        for (int j = 0; j < 4; ++j)
            #pragma unroll
            for (int e = 0; e < 4; ++e) acc[i][j][e] = 0.0f;

    #pragma unroll
    for (int ks = 0; ks < 4; ++ks) {
        const int k0 = ks * 8;
        uint32_t a[2][4];
        #pragma unroll
        for (int mt = 0; mt < 2; ++mt) {
            a[mt][0] = sCK[(k0 + tig)     * CK_STR + mt * 16 + g];
            a[mt][1] = sCK[(k0 + tig)     * CK_STR + mt * 16 + g + 8];
            a[mt][2] = sCK[(k0 + tig + 4) * CK_STR + mt * 16 + g];
            a[mt][3] = sCK[(k0 + tig + 4) * CK_STR + mt * 16 + g + 8];
        }
        #pragma unroll
        for (int nt = 0; nt < 4; ++nt) {
            uint32_t b0 = sS[(k0 + tig)     * SH_STR + nt * 8 + g];
            uint32_t b1 = sS[(k0 + tig + 4) * SH_STR + nt * 8 + g];
            mma_tf32(acc[0][nt][0], acc[0][nt][1], acc[0][nt][2], acc[0][nt][3],
                     a[0][0], a[0][1], a[0][2], a[0][3], b0, b1);
            mma_tf32(acc[1][nt][0], acc[1][nt][1], acc[1][nt][2], acc[1][nt][3],
                     a[1][0], a[1][1], a[1][2], a[1][3], b0, b1);
        }
    }
    __syncwarp();

    uint32_t* sY = sSh[warp];
    #pragma unroll
    for (int mt = 0; mt < 2; ++mt) {
        #pragma unroll
        for (int nt = 0; nt < 4; ++nt) {
            const int c  = nt * 8 + 2 * tig;
            const int r0 = mt * 16 + g;
            sY[(c)     * SY_STR + r0]     = __float_as_uint(acc[mt][nt][0]);
            sY[(c + 1) * SY_STR + r0]     = __float_as_uint(acc[mt][nt][1]);
            sY[(c)     * SY_STR + r0 + 8] = __float_as_uint(acc[mt][nt][2]);
            sY[(c + 1) * SY_STR + r0 + 8] = __float_as_uint(acc[mt][nt][3]);
        }
    }
    __syncwarp();

    float4* outp = (float4*)g_ypow + (size_t)bv * 128 + warp * 64;
    #pragma unroll
    for (int i = 0; i < 2; ++i) {
        const int c = i * 16 + (lane >> 1);
        const int r = lane & 1;
        const uint32_t* col = sY + c * SY_STR + r * 16;
        uint4 q0 = *(const uint4*)&col[0];
        uint4 q1 = *(const uint4*)&col[4];
        uint4 q2 = *(const uint4*)&col[8];
        uint4 q3 = *(const uint4*)&col[12];
        float v0  = __uint_as_float(q0.x), v1  = __uint_as_float(q0.y);
        float v2  = __uint_as_float(q0.z), v3  = __uint_as_float(q0.w);
        float v4  = __uint_as_float(q1.x), v5  = __uint_as_float(q1.y);
        float v6  = __uint_as_float(q1.z), v7  = __uint_as_float(q1.w);
        float v8  = __uint_as_float(q2.x), v9  = __uint_as_float(q2.y);
        float v10 = __uint_as_float(q2.z), v11 = __uint_as_float(q2.w);
        float v12 = __uint_as_float(q3.x), v13 = __uint_as_float(q3.y);
        float v14 = __uint_as_float(q3.z), v15 = __uint_as_float(q3.w);
        float l0 = v0 * v0;
        float l1 = v1 * v1 + v2 * v2 + v3 * v3;
        float l2 = v4 * v4 + v5 * v5 + v6 * v6 + v7 * v7 + v8 * v8;
        float l3 = v9 * v9 + v10 * v10 + v11 * v11 + v12 * v12
                 + v13 * v13 + v14 * v14 + v15 * v15;
        float4 o;
        o.x = __uint_as_float(f2tf32(sqclip(l0)));
        o.y = __uint_as_float(f2tf32(sqclip(l1)));
        o.z = __uint_as_float(f2tf32(sqclip(l2)));
        o.w = __uint_as_float(f2tf32(sqclip(l3)));
        outp[c * 2 + r] = o;
    }
}

// ---------------------------------------------------------------------------
// Kernel 2: out = ypow * W^T + bias, relu.  CTA 128 thr, tile 64m x 128n,
// 4-stage cp.async pipeline (kT=16, 1 sync/iter), XOR-swizzled tiles,
// ldmatrix.x4 fragment loads.  Warp = 32m x 64n.
// ---------------------------------------------------------------------------
#define KT     16
#define NKT    (K2 / KT)    // 32
#define M_BLK  64
#define N_BLK  128

// word offset of (row, 16B-chunk c) in a tile with 16-word rows:
//   row*16 + (c ^ ((row>>1)&3))*4   -- conflict-free for cp.async + LDSM
__device__ __forceinline__ int swz(int row, int c) {
    return row * 16 + ((c ^ ((row >> 1) & 3)) << 2);
}

__global__ __launch_bounds__(128, 4)
void out_gemm_kernel(const float* __restrict__ bias,
                     float* __restrict__ out)
{
    __shared__ uint32_t sA[4][M_BLK * KT];   // 4 x 4KB
    __shared__ uint32_t sB[4][N_BLK * KT];   // 4 x 8KB   total 48KB

    const int tid  = threadIdx.x;
    const int warp = tid >> 5;
    const int lane = tid & 31;
    const int g    = lane >> 2;
    const int tig  = lane & 3;
    const int wm   = warp >> 1;        // 0..1
    const int wn   = warp & 1;         // 0..1
    const int m0   = blockIdx.x * M_BLK;
    const int quad = lane >> 3;
    const int rin  = lane & 7;

    const uint32_t* yp = (const uint32_t*)g_ypow;

    float acc[2][8][4];
    #pragma unroll
    for (int a = 0; a < 2; ++a)
        #pragma unroll
        for (int b = 0; b < 8; ++b)
            #pragma unroll
            for (int c = 0; c < 4; ++c) acc[a][b][c] = 0.0f;

    auto stage = [&](int kt, int st) {
        #pragma unroll
        for (int i = 0; i < 2; ++i) {          // A: 256 chunks
            int id = tid + i * 128;
            int row = id >> 2, c = id & 3;
            cp_async16(smem_u32(&sA[st][swz(row, c)]),
                       yp + (size_t)(m0 + row) * K2 + kt * KT + c * 4);
        }
        #pragma unroll
        for (int i = 0; i < 4; ++i) {          // B: 512 chunks
            int id = tid + i * 128;
            int row = id >> 2, c = id & 3;
            cp_async16(smem_u32(&sB[st][swz(row, c)]),
                       g_W + (size_t)row * K2 + kt * KT + c * 4);
        }
        asm volatile("cp.async.commit_group;");
    };

    stage(0, 0);
    stage(1, 1);
    stage(2, 2);

    for (int kt = 0; kt < NKT; ++kt) {
        asm volatile("cp.async.wait_group 2;");
        __syncthreads();
        if (kt + 3 < NKT) stage(kt + 3, (kt + 3) & 3);
        else asm volatile("cp.async.commit_group;");   // keep group count exact
        const int st = kt & 3;

        #pragma unroll
        for (int ks = 0; ks < 2; ++ks) {
            uint32_t a[2][4];
            #pragma unroll
            for (int mi = 0; mi < 2; ++mi) {
                // tiles: (rows lo/hi via quad&1, k-half via quad>>1)
                int row = wm * 32 + mi * 16 + (quad & 1) * 8 + rin;
                int ch  = ks * 2 + (quad >> 1);
                ldsm_x4(a[mi], smem_u32(&sA[st][swz(row, ch)]));
            }
            uint32_t b[4][4];
            #pragma unroll
            for (int p = 0; p < 4; ++p) {
                // tiles: (k-half via quad&1, rows lo/hi via quad>>1)
                int row = wn * 64 + p * 16 + (quad >> 1) * 8 + rin;
                int ch  = ks * 2 + (quad & 1);
                ldsm_x4(b[p], smem_u32(&sB[st][swz(row, ch)]));
            }
            #pragma unroll
            for (int p = 0; p < 4; ++p) {
                mma_tf32(acc[0][2*p][0], acc[0][2*p][1], acc[0][2*p][2], acc[0][2*p][3],
                         a[0][0], a[0][1], a[0][2], a[0][3], b[p][0], b[p][1]);
                mma_tf32(acc[0][2*p+1][0], acc[0][2*p+1][1], acc[0][2*p+1][2], acc[0][2*p+1][3],
                         a[0][0], a[0][1], a[0][2], a[0][3], b[p][2], b[p][3]);
                mma_tf32(acc[1][2*p][0], acc[1][2*p][1], acc[1][2*p][2], acc[1][2*p][3],
                         a[1][0], a[1][1], a[1][2], a[1][3], b[p][0], b[p][1]);
                mma_tf32(acc[1][2*p+1][0], acc[1][2*p+1][1], acc[1][2*p+1][2], acc[1][2*p+1][3],
                         a[1][0], a[1][1], a[1][2], a[1][3], b[p][2], b[p][3]);
            }
        }
    }

    // Epilogue: bias + relu, float2 stores
    #pragma unroll
    for (int nt = 0; nt < 8; ++nt) {
        const int col = wn * 64 + nt * 8 + 2 * tig;
        const float b0 = __ldg(&bias[col]);
        const float b1 = __ldg(&bias[col + 1]);
        #pragma unroll
        for (int mi = 0; mi < 2; ++mi) {
            const int row = m0 + wm * 32 + mi * 16 + g;
            float2 v0, v1;
            v0.x = fmaxf(acc[mi][nt][0] + b0, 0.0f);
            v0.y = fmaxf(acc[mi][nt][1] + b1, 0.0f);
            v1.x = fmaxf(acc[mi][nt][2] + b0, 0.0f);
            v1.y = fmaxf(acc[mi][nt][3] + b1, 0.0f);
            *(float2*)(out + (size_t)row * COUT + col)       = v0;
            *(float2*)(out + (size_t)(row + 8) * COUT + col) = v1;
        }
    }
}

extern "C" void kernel_launch(void* const* d_in, const int* in_sizes, int n_in,
                              void* d_out, int out_size)
{
    const float* signal = (const float*)d_in[0];
    const int*   pidx   = (const int*)  d_in[1];
    const float* convk  = (const float*)d_in[2];
    const float* W      = (const float*)d_in[3];
    const float* bias   = (const float*)d_in[4];
    float* out = (float*)d_out;

    ypow_kernel<<<BV, 64>>>(signal, pidx, convk, W);
    out_gemm_kernel<<<BV / M_BLK, 128>>>(bias, out);
}